// round 2
// baseline (speedup 1.0000x reference)
#include <cuda_runtime.h>
#include <cuda_bf16.h>

#define B_ 8
#define P_ 4096
#define G_ 96
#define NT 1024
#define CPT (P_ / NT)
#define BIGF 1e9f
#define INFF 3.402823466e+38f

// Scratch: transposed cost matrix [B, G, P] (device global — no allocs allowed)
__device__ float g_costT[(size_t)B_ * G_ * P_];

// ---------------------------------------------------------------------------
// Kernel 1: fused cost + transpose.  costT[b][g][p] = cd[b][p][g] - 2*gi[b][p][g]
// ---------------------------------------------------------------------------
__global__ void cost_transpose_kernel(const float* __restrict__ cd,
                                      const float* __restrict__ gi) {
    __shared__ float tile[32][33];
    const int b = blockIdx.z;
    const int p0 = blockIdx.x * 32;
    const int g0 = blockIdx.y * 32;   // G_=96 divides by 32 exactly
    const int tx = threadIdx.x, ty = threadIdx.y;

    size_t iidx = ((size_t)b * P_ + (p0 + ty)) * G_ + (g0 + tx);
    float c = cd[iidx];
    float g = gi[iidx];
    // 2*g is exact in fp32 -> c - 2g rounds identically to reference
    tile[ty][tx] = c - 2.0f * g;
    __syncthreads();

    g_costT[((size_t)b * G_ + (g0 + ty)) * P_ + (p0 + tx)] = tile[tx][ty];
}

// ---------------------------------------------------------------------------
// Kernel 2: one block per batch. Jonker-Volgenant shortest augmenting path,
// bit-for-bit following the reference's operation order.
// ---------------------------------------------------------------------------
__global__ __launch_bounds__(NT, 1)
void matcher_kernel(const int* __restrict__ nactual,
                    float* __restrict__ out) {
    extern __shared__ char smem[];
    float* v        = (float*)smem;                    // [P_]
    float* shortest = v + P_;                          // [P_]
    int*   path     = (int*)(shortest + P_);           // [P_]
    int*   row4col  = path + P_;                       // [P_]
    float* u        = (float*)(row4col + P_);          // [G_]
    int*   col4row  = (int*)(u + G_);                  // [G_]
    float* redv     = (float*)(col4row + G_);          // [32]
    int*   redi     = (int*)(redv + 32);               // [32]
    unsigned char* SC = (unsigned char*)(redi + 32);   // [P_]
    unsigned char* SR = SC + P_;                       // [G_]

    __shared__ int   s_cur;
    __shared__ int   s_sink;
    __shared__ float s_minval;

    const int b = blockIdx.x;
    const int t = threadIdx.x;
    const float* cost = g_costT + (size_t)b * G_ * P_;
    const int nact = nactual[b];

    for (int j = t; j < P_; j += NT) { v[j] = 0.0f; row4col[j] = -1; }
    if (t < G_) { u[t] = 0.0f; col4row[t] = -1; }
    __syncthreads();

    for (int i = 0; i < nact; ++i) {
        for (int j = t; j < P_; j += NT) { shortest[j] = BIGF; path[j] = -1; SC[j] = 0; }
        if (t < G_) SR[t] = 0;
        if (t == 0) { s_cur = i; s_sink = -1; s_minval = 0.0f; }
        __syncthreads();

        // Dijkstra over columns until a free column (sink) is found
        while (true) {
            if (s_sink >= 0) break;
            const int   cur    = s_cur;
            const float minval = s_minval;
            if (t == 0) SR[cur] = 1;
            const float ucur = u[cur];
            const float* crow = cost + (size_t)cur * P_;

            float bestv = INFF;
            int   bestj = P_;
            #pragma unroll
            for (int k = 0; k < CPT; k++) {
                const int j = t + k * NT;
                float sh = shortest[j];
                float cand;
                if (!SC[j]) {
                    // reference order: ((minval + cost) - u[cur]) - v
                    float red = ((minval + crow[j]) - ucur) - v[j];
                    if (red < sh) { sh = red; shortest[j] = red; path[j] = cur; }
                    cand = sh;
                } else {
                    cand = BIGF;
                }
                if (cand < bestv) { bestv = cand; bestj = j; }   // j ascending: keeps first
            }
            #pragma unroll
            for (int off = 16; off; off >>= 1) {
                float ov = __shfl_down_sync(0xffffffffu, bestv, off);
                int   oj = __shfl_down_sync(0xffffffffu, bestj, off);
                if (ov < bestv || (ov == bestv && oj < bestj)) { bestv = ov; bestj = oj; }
            }
            if ((t & 31) == 0) { redv[t >> 5] = bestv; redi[t >> 5] = bestj; }
            __syncthreads();
            if (t < 32) {
                bestv = redv[t]; bestj = redi[t];
                #pragma unroll
                for (int off = 16; off; off >>= 1) {
                    float ov = __shfl_down_sync(0xffffffffu, bestv, off);
                    int   oj = __shfl_down_sync(0xffffffffu, bestj, off);
                    if (ov < bestv || (ov == bestv && oj < bestj)) { bestv = ov; bestj = oj; }
                }
                if (t == 0) {
                    s_minval = bestv;
                    SC[bestj] = 1;
                    int r = row4col[bestj];
                    if (r < 0) s_sink = bestj; else s_cur = r;
                }
            }
            __syncthreads();
        }

        // dual updates (before augmentation, as in reference)
        const float minval = s_minval;
        if (t == 0) u[i] += minval;
        if (t < G_ && t != i && SR[t]) {
            int c4 = col4row[t]; if (c4 < 0) c4 = 0;        // clip as in reference
            u[t] = (u[t] + minval) - shortest[c4];
        }
        for (int j = t; j < P_; j += NT)
            if (SC[j]) v[j] = v[j] - (minval - shortest[j]);
        __syncthreads();

        // augment alternating path (sequential, tiny)
        if (t == 0) {
            int j = s_sink;
            while (true) {
                int r = path[j];
                row4col[j] = r;
                int jn = col4row[r];
                col4row[r] = j;
                if (r == i) break;
                j = jn;
            }
        }
        __syncthreads();
    }

    // write outputs for this batch — combined output dtype is float32:
    //   region 0: per_prop_gt_inds as float, region 1: matched mask
    float* oi = out + (size_t)b * P_;
    float* om = out + (size_t)B_ * P_ + (size_t)b * P_;
    for (int j = t; j < P_; j += NT) { oi[j] = 0.0f; om[j] = 0.0f; }
    __syncthreads();
    if (t < G_ && t < nact) {
        int p = col4row[t];
        if (p >= 0) { oi[p] = (float)t; om[p] = 1.0f; }
    }
}

// ---------------------------------------------------------------------------
static const int MATCHER_SMEM =
    (P_ * 4) * 4              /* v, shortest, path, row4col */
    + G_ * 4 * 2              /* u, col4row */
    + 32 * 4 * 2              /* redv, redi */
    + P_                      /* SC */
    + G_ + 64;                /* SR + pad */

extern "C" void kernel_launch(void* const* d_in, const int* in_sizes, int n_in,
                              void* d_out, int out_size) {
    const float* cd   = (const float*)d_in[0];   // center_dist [B,P,G]
    const float* gi   = (const float*)d_in[1];   // gious       [B,P,G]
    const int*   nact = (const int*)d_in[2];     // nactual_gt  [B]

    float* out = (float*)d_out;                  // [2, B, P] float32

    dim3 tb(32, 32);
    dim3 gb(P_ / 32, G_ / 32, B_);
    cost_transpose_kernel<<<gb, tb>>>(cd, gi);

    cudaFuncSetAttribute(matcher_kernel,
                         cudaFuncAttributeMaxDynamicSharedMemorySize, MATCHER_SMEM);
    matcher_kernel<<<B_, NT, MATCHER_SMEM>>>(nact, out);
}

// round 3
// speedup vs baseline: 1.5144x; 1.5144x over previous
#include <cuda_runtime.h>
#include <cuda_bf16.h>

#define B_ 8
#define P_ 4096
#define G_ 96
#define NT 256
#define NW (NT / 32)
#define CPT (P_ / NT)          // 16 columns per thread, statically owned
#define BIGF 1e9f
#define INFF 3.402823466e+38f

__device__ float g_costT[(size_t)B_ * G_ * P_];

// ---------------------------------------------------------------------------
// Kernel 1: fused cost + transpose.  costT[b][g][p] = cd[b][p][g] - 2*gi[b][p][g]
// ---------------------------------------------------------------------------
__global__ void cost_transpose_kernel(const float* __restrict__ cd,
                                      const float* __restrict__ gi) {
    __shared__ float tile[32][33];
    const int b = blockIdx.z;
    const int p0 = blockIdx.x * 32;
    const int g0 = blockIdx.y * 32;
    const int tx = threadIdx.x, ty = threadIdx.y;

    size_t iidx = ((size_t)b * P_ + (p0 + ty)) * G_ + (g0 + tx);
    float c = cd[iidx];
    float g = gi[iidx];
    tile[ty][tx] = c - 2.0f * g;     // 2*g exact in fp32 -> identical rounding
    __syncthreads();
    g_costT[((size_t)b * G_ + (g0 + ty)) * P_ + (p0 + tx)] = tile[tx][ty];
}

// ---------------------------------------------------------------------------
// Kernel 2: one block per batch, register-resident JV shortest augmenting path.
// Per Dijkstra iteration: ONE __syncthreads; argmin finalized redundantly by
// every thread from NW warp partials (parity double-buffered).
// ---------------------------------------------------------------------------
__global__ __launch_bounds__(NT, 1)
void matcher_kernel(const int* __restrict__ nactual,
                    float* __restrict__ out) {
    extern __shared__ char smem[];
    int*   row4col  = (int*)smem;                      // [P_]
    float* sh_dump  = (float*)(row4col + P_);          // [P_] shortest (end of aug)
    int*   path_dump= (int*)(sh_dump + P_);            // [P_] path     (end of aug)
    float* u        = (float*)(path_dump + P_);        // [G_]
    int*   col4row  = (int*)(u + G_);                  // [G_]
    float* redv     = (float*)(col4row + G_);          // [2][NW]
    int*   redi     = (int*)(redv + 2 * NW);           // [2][NW]
    unsigned char* SR = (unsigned char*)(redi + 2 * NW); // [G_]

    const int b = blockIdx.x;
    const int t = threadIdx.x;
    const float* cost = g_costT + (size_t)b * G_ * P_;
    const int nact = nactual[b];

    // register-resident per-column state (column j = t + k*NT)
    float vreg[CPT];
    float shreg[CPT];
    int   pathreg[CPT];
    unsigned int scmask;

    #pragma unroll
    for (int k = 0; k < CPT; k++) vreg[k] = 0.0f;
    for (int j = t; j < P_; j += NT) row4col[j] = -1;
    if (t < G_) { u[t] = 0.0f; col4row[t] = -1; }
    __syncthreads();

    for (int i = 0; i < nact; ++i) {
        #pragma unroll
        for (int k = 0; k < CPT; k++) { shreg[k] = BIGF; pathreg[k] = -1; }
        scmask = 0u;
        if (t < G_) SR[t] = 0;

        int   cur    = i;          // tracked redundantly by every thread
        float minval = 0.0f;
        int   sink   = -1;
        int   parity = 0;
        __syncthreads();           // SR reset + previous augment visible

        while (sink < 0) {
            if (t == 0) SR[cur] = 1;
            const float ucur = u[cur];
            const float* crow = cost + (size_t)cur * P_;

            // batched loads for MLP, then compute
            float c[CPT];
            #pragma unroll
            for (int k = 0; k < CPT; k++) c[k] = __ldg(crow + t + k * NT);

            float bestv = INFF;
            int   bestj = P_;
            #pragma unroll
            for (int k = 0; k < CPT; k++) {
                if (!((scmask >> k) & 1u)) {
                    // reference order: ((minval + cost) - u[cur]) - v
                    float red = ((minval + c[k]) - ucur) - vreg[k];
                    if (red < shreg[k]) { shreg[k] = red; pathreg[k] = cur; }
                    if (shreg[k] < bestv) { bestv = shreg[k]; bestj = t + k * NT; }
                }
            }
            // warp argmin (first-index tiebreak)
            #pragma unroll
            for (int off = 16; off; off >>= 1) {
                float ov = __shfl_down_sync(0xffffffffu, bestv, off);
                int   oj = __shfl_down_sync(0xffffffffu, bestj, off);
                if (ov < bestv || (ov == bestv && oj < bestj)) { bestv = ov; bestj = oj; }
            }
            if ((t & 31) == 0) { redv[parity * NW + (t >> 5)] = bestv; redi[parity * NW + (t >> 5)] = bestj; }
            __syncthreads();

            // every thread finalizes the argmin redundantly (broadcast LDS)
            bestv = redv[parity * NW];
            bestj = redi[parity * NW];
            #pragma unroll
            for (int w = 1; w < NW; w++) {
                float ov = redv[parity * NW + w];
                int   oj = redi[parity * NW + w];
                if (ov < bestv || (ov == bestv && oj < bestj)) { bestv = ov; bestj = oj; }
            }
            minval = bestv;
            if ((bestj & (NT - 1)) == t) scmask |= 1u << (bestj >> 8);  // bestj/NT
            int r = row4col[bestj];
            if (r < 0) sink = bestj; else cur = r;
            parity ^= 1;
        }

        // dump register state needed cross-thread
        #pragma unroll
        for (int k = 0; k < CPT; k++) {
            sh_dump[t + k * NT]   = shreg[k];
            path_dump[t + k * NT] = pathreg[k];
        }
        __syncthreads();

        // dual updates (exact reference associations)
        if (t == 0) u[i] += minval;
        if (t < G_ && t != i && SR[t]) {
            int c4 = col4row[t]; if (c4 < 0) c4 = 0;   // clip as in reference
            u[t] = (u[t] + minval) - sh_dump[c4];
        }
        #pragma unroll
        for (int k = 0; k < CPT; k++)
            if ((scmask >> k) & 1u) vreg[k] = vreg[k] - (minval - shreg[k]);
        // augment alternating path (needs path_dump; u writes independent)
        __syncthreads();
        if (t == 0) {
            int j = sink;
            while (true) {
                int r = path_dump[j];
                row4col[j] = r;
                int jn = col4row[r];
                col4row[r] = j;
                if (r == i) break;
                j = jn;
            }
        }
        __syncthreads();
    }

    // outputs: region 0 = per_prop_gt_inds (as float), region 1 = matched mask
    float* oi = out + (size_t)b * P_;
    float* om = out + (size_t)B_ * P_ + (size_t)b * P_;
    for (int j = t; j < P_; j += NT) { oi[j] = 0.0f; om[j] = 0.0f; }
    __syncthreads();
    if (t < G_ && t < nact) {
        int p = col4row[t];
        if (p >= 0) { oi[p] = (float)t; om[p] = 1.0f; }
    }
}

// ---------------------------------------------------------------------------
static const int MATCHER_SMEM =
    P_ * 4 * 3                 /* row4col, sh_dump, path_dump */
    + G_ * 4 * 2               /* u, col4row */
    + 2 * NW * 4 * 2           /* redv, redi (double-buffered) */
    + G_ + 64;                 /* SR + pad */

extern "C" void kernel_launch(void* const* d_in, const int* in_sizes, int n_in,
                              void* d_out, int out_size) {
    const float* cd   = (const float*)d_in[0];
    const float* gi   = (const float*)d_in[1];
    const int*   nact = (const int*)d_in[2];

    float* out = (float*)d_out;                  // [2, B, P] float32

    dim3 tb(32, 32);
    dim3 gb(P_ / 32, G_ / 32, B_);
    cost_transpose_kernel<<<gb, tb>>>(cd, gi);

    cudaFuncSetAttribute(matcher_kernel,
                         cudaFuncAttributeMaxDynamicSharedMemorySize, MATCHER_SMEM);
    matcher_kernel<<<B_, NT, MATCHER_SMEM>>>(nact, out);
}

// round 4
// speedup vs baseline: 1.5447x; 1.0200x over previous
#include <cuda_runtime.h>
#include <cuda_bf16.h>

#define B_ 8
#define P_ 4096
#define G_ 96
#define NT 256
#define NW (NT / 32)
#define CPT (P_ / NT)          // 16 columns per thread, statically owned
#define BIGF 1e9f
#define INFF 3.402823466e+38f

__device__ float g_costT[(size_t)B_ * G_ * P_];

// order-preserving float<->uint bijection (ascending)
__device__ __forceinline__ unsigned int f2ord(float f) {
    unsigned int u = __float_as_uint(f);
    return ((int)u < 0) ? ~u : (u ^ 0x80000000u);
}
__device__ __forceinline__ float ord2f(unsigned int k) {
    unsigned int u = (k & 0x80000000u) ? (k ^ 0x80000000u) : ~k;
    return __uint_as_float(u);
}

// ---------------------------------------------------------------------------
// Kernel 1: fused cost + transpose.  costT[b][g][p] = cd[b][p][g] - 2*gi[b][p][g]
// ---------------------------------------------------------------------------
__global__ void cost_transpose_kernel(const float* __restrict__ cd,
                                      const float* __restrict__ gi) {
    __shared__ float tile[32][33];
    const int b = blockIdx.z;
    const int p0 = blockIdx.x * 32;
    const int g0 = blockIdx.y * 32;
    const int tx = threadIdx.x, ty = threadIdx.y;

    size_t iidx = ((size_t)b * P_ + (p0 + ty)) * G_ + (g0 + tx);
    float c = cd[iidx];
    float g = gi[iidx];
    tile[ty][tx] = c - 2.0f * g;     // 2*g exact in fp32 -> identical rounding
    __syncthreads();
    g_costT[((size_t)b * G_ + (g0 + ty)) * P_ + (p0 + tx)] = tile[tx][ty];
}

// ---------------------------------------------------------------------------
// Kernel 2: one block per batch, register-resident JV shortest augmenting path.
// One barrier per Dijkstra iteration; REDUX.SYNC warp argmin; warp partials
// carry (key, j, row4col[j], u[row4col[j]]) so the post-barrier chain is short.
// ---------------------------------------------------------------------------
__global__ __launch_bounds__(NT, 1)
void matcher_kernel(const int* __restrict__ nactual,
                    float* __restrict__ out) {
    extern __shared__ char smem[];
    int*   row4col  = (int*)smem;                      // [P_]
    float* sh_dump  = (float*)(row4col + P_);          // [P_]
    int*   path_dump= (int*)(sh_dump + P_);            // [P_]
    float* u        = (float*)(path_dump + P_);        // [G_]
    int*   col4row  = (int*)(u + G_);                  // [G_]
    uint4* partials = (uint4*)(col4row + G_);          // [2][NW] (16B aligned: offsets all mult of 16)
    unsigned char* SR = (unsigned char*)(partials + 2 * NW); // [G_]

    const int b = blockIdx.x;
    const int t = threadIdx.x;
    const float* cost = g_costT + (size_t)b * G_ * P_;
    const int nact = nactual[b];

    float vreg[CPT];
    float shreg[CPT];
    int   pathreg[CPT];
    unsigned int scmask;

    #pragma unroll
    for (int k = 0; k < CPT; k++) vreg[k] = 0.0f;
    for (int j = t; j < P_; j += NT) row4col[j] = -1;
    if (t < G_) { u[t] = 0.0f; col4row[t] = -1; }

    for (int i = 0; i < nact; ++i) {
        #pragma unroll
        for (int k = 0; k < CPT; k++) { shreg[k] = BIGF; pathreg[k] = -1; }
        scmask = 0u;
        if (t < G_) SR[t] = 0;
        __syncthreads();           // barrier A: init/augment/u-writes visible

        int   cur    = i;
        float ucur   = u[i];
        float minval = 0.0f;
        int   sink   = -1;
        int   parity = 0;

        while (sink < 0) {
            if (t == 0) SR[cur] = 1;
            const float* crow = cost + (size_t)cur * P_;

            float c[CPT];
            #pragma unroll
            for (int k = 0; k < CPT; k++) c[k] = __ldg(crow + t + k * NT);

            float bestv = INFF;
            int   bestj = P_;
            #pragma unroll
            for (int k = 0; k < CPT; k++) {
                if (!((scmask >> k) & 1u)) {
                    // reference order: ((minval + cost) - u[cur]) - v
                    float red = ((minval + c[k]) - ucur) - vreg[k];
                    if (red < shreg[k]) { shreg[k] = red; pathreg[k] = cur; }
                    if (shreg[k] < bestv) { bestv = shreg[k]; bestj = t + k * NT; }
                }
            }
            // warp argmin via 2x REDUX.SYNC (lexicographic (key, j) == first-index)
            unsigned int key    = f2ord(bestv);
            unsigned int minkey = __reduce_min_sync(0xffffffffu, key);
            unsigned int jc     = (key == minkey) ? (unsigned int)bestj : 0xffffffffu;
            unsigned int minj   = __reduce_min_sync(0xffffffffu, jc);

            if ((t & 31) == 0) {
                int r = row4col[minj];
                float ur = (r >= 0) ? u[r] : 0.0f;
                partials[parity * NW + (t >> 5)] =
                    make_uint4(minkey, minj, (unsigned int)r, __float_as_uint(ur));
            }
            __syncthreads();

            // every thread reduces the NW partials redundantly (broadcast LDS.128)
            uint4 best = partials[parity * NW];
            #pragma unroll
            for (int w = 1; w < NW; w++) {
                uint4 pw = partials[parity * NW + w];
                if (pw.x < best.x || (pw.x == best.x && pw.y < best.y)) best = pw;
            }
            minval = ord2f(best.x);
            int bj = (int)best.y;
            if ((bj & (NT - 1)) == t) scmask |= 1u << (bj >> 8);  // bj / NT
            if ((int)best.z < 0) { sink = bj; }
            else { cur = (int)best.z; ucur = __uint_as_float(best.w); }
            parity ^= 1;
        }

        // dump register state needed cross-thread
        #pragma unroll
        for (int k = 0; k < CPT; k++) {
            sh_dump[t + k * NT]   = shreg[k];
            path_dump[t + k * NT] = pathreg[k];
        }
        __syncthreads();           // barrier B

        // dual updates (exact reference associations, pre-augment col4row)
        if (t == 0) u[i] += minval;
        if (t < G_ && t != i && SR[t]) {
            int c4 = col4row[t]; if (c4 < 0) c4 = 0;   // clip as in reference
            u[t] = (u[t] + minval) - sh_dump[c4];
        }
        #pragma unroll
        for (int k = 0; k < CPT; k++)
            if ((scmask >> k) & 1u) vreg[k] = vreg[k] - (minval - shreg[k]);
        __syncthreads();           // barrier C

        if (t == 0) {
            int j = sink;
            while (true) {
                int r = path_dump[j];
                row4col[j] = r;
                int jn = col4row[r];
                col4row[r] = j;
                if (r == i) break;
                j = jn;
            }
        }
        // next iteration's barrier A orders the augment writes
    }

    // outputs: region 0 = per_prop_gt_inds (as float), region 1 = matched mask
    float* oi = out + (size_t)b * P_;
    float* om = out + (size_t)B_ * P_ + (size_t)b * P_;
    for (int j = t; j < P_; j += NT) { oi[j] = 0.0f; om[j] = 0.0f; }
    __syncthreads();
    if (t < G_ && t < nact) {
        int p = col4row[t];
        if (p >= 0) { oi[p] = (float)t; om[p] = 1.0f; }
    }
}

// ---------------------------------------------------------------------------
static const int MATCHER_SMEM =
    P_ * 4 * 3                 /* row4col, sh_dump, path_dump */
    + G_ * 4 * 2               /* u, col4row */
    + 2 * NW * 16              /* uint4 partials (double-buffered) */
    + G_ + 64;                 /* SR + pad */

extern "C" void kernel_launch(void* const* d_in, const int* in_sizes, int n_in,
                              void* d_out, int out_size) {
    const float* cd   = (const float*)d_in[0];
    const float* gi   = (const float*)d_in[1];
    const int*   nact = (const int*)d_in[2];

    float* out = (float*)d_out;                  // [2, B, P] float32

    dim3 tb(32, 32);
    dim3 gb(P_ / 32, G_ / 32, B_);
    cost_transpose_kernel<<<gb, tb>>>(cd, gi);

    cudaFuncSetAttribute(matcher_kernel,
                         cudaFuncAttributeMaxDynamicSharedMemorySize, MATCHER_SMEM);
    matcher_kernel<<<B_, NT, MATCHER_SMEM>>>(nact, out);
}

// round 5
// speedup vs baseline: 9.3519x; 6.0542x over previous
#include <cuda_runtime.h>
#include <cuda_bf16.h>

#define B_ 8
#define P_ 4096
#define G_ 96
#define NT 256
#define NW (NT / 32)
#define CPT (P_ / NT)
#define BIGF 1e9f
#define INFF 3.402823466e+38f

__device__ float g_costT[(size_t)B_ * G_ * P_];
__device__ unsigned long long g_rowarg[B_ * G_];   // packed (f2ord(min)<<32) | argmin

__device__ __forceinline__ unsigned int f2ord(float f) {
    unsigned int u = __float_as_uint(f);
    return ((int)u < 0) ? ~u : (u ^ 0x80000000u);
}
__device__ __forceinline__ float ord2f(unsigned int k) {
    unsigned int u = (k & 0x80000000u) ? (k ^ 0x80000000u) : ~k;
    return __uint_as_float(u);
}

// ---------------------------------------------------------------------------
// Kernel 1: fused cost + transpose.  costT[b][g][p] = cd[b][p][g] - 2*gi[b][p][g]
// ---------------------------------------------------------------------------
__global__ void cost_transpose_kernel(const float* __restrict__ cd,
                                      const float* __restrict__ gi) {
    __shared__ float tile[32][33];
    const int b = blockIdx.z;
    const int p0 = blockIdx.x * 32;
    const int g0 = blockIdx.y * 32;
    const int tx = threadIdx.x, ty = threadIdx.y;

    size_t iidx = ((size_t)b * P_ + (p0 + ty)) * G_ + (g0 + tx);
    float c = cd[iidx];
    float g = gi[iidx];
    tile[ty][tx] = c - 2.0f * g;     // 2*g exact in fp32
    __syncthreads();
    g_costT[((size_t)b * G_ + (g0 + ty)) * P_ + (p0 + tx)] = tile[tx][ty];
}

// ---------------------------------------------------------------------------
// Kernel 2: per-row argmin over P columns. grid=(G_, B_), block=NT.
// Packed lexicographic (key, j) min == first-index argmin.
// ---------------------------------------------------------------------------
__global__ __launch_bounds__(NT, 8)
void row_argmin_kernel() {
    __shared__ unsigned long long part[NW];
    const int g = blockIdx.x, b = blockIdx.y;
    const int t = threadIdx.x;
    const float* crow = g_costT + ((size_t)b * G_ + g) * P_;

    float bestv = INFF;
    int   bestj = 0;
    #pragma unroll
    for (int k = 0; k < CPT; k++) {
        float c = __ldg(crow + t + k * NT);
        if (c < bestv) { bestv = c; bestj = t + k * NT; }  // ascending j keeps first
    }
    unsigned long long pk = ((unsigned long long)f2ord(bestv) << 32) | (unsigned int)bestj;
    #pragma unroll
    for (int off = 16; off; off >>= 1) {
        unsigned long long o = __shfl_down_sync(0xffffffffu, pk, off);
        if (o < pk) pk = o;
    }
    if ((t & 31) == 0) part[t >> 5] = pk;
    __syncthreads();
    if (t == 0) {
        #pragma unroll
        for (int w = 1; w < NW; w++) if (part[w] < pk) pk = part[w];
        g_rowarg[b * G_ + g] = pk;
    }
}

// ---------------------------------------------------------------------------
// Kernel 3: one block per batch. Greedy dual-feasible init (u[i]=rowmin, v=0),
// then JV shortest augmenting path only for conflicted rows.
// ---------------------------------------------------------------------------
__global__ __launch_bounds__(NT, 1)
void matcher_kernel(const int* __restrict__ nactual,
                    float* __restrict__ out) {
    extern __shared__ char smem[];
    int*   row4col  = (int*)smem;                      // [P_]
    float* sh_dump  = (float*)(row4col + P_);          // [P_]
    int*   path_dump= (int*)(sh_dump + P_);            // [P_] (aliased as colowner in greedy)
    float* u        = (float*)(path_dump + P_);        // [G_]
    int*   col4row  = (int*)(u + G_);                  // [G_]
    uint4* partials = (uint4*)(col4row + G_);          // [2][NW]
    unsigned char* SR = (unsigned char*)(partials + 2 * NW); // [G_]

    const int b = blockIdx.x;
    const int t = threadIdx.x;
    const float* cost = g_costT + (size_t)b * G_ * P_;
    const int nact = nactual[b];

    float vreg[CPT];
    float shreg[CPT];
    int   pathreg[CPT];
    unsigned int scmask;

    #pragma unroll
    for (int k = 0; k < CPT; k++) vreg[k] = 0.0f;
    int* colowner = path_dump;
    for (int j = t; j < P_; j += NT) { row4col[j] = -1; colowner[j] = 0x7fffffff; }
    if (t < G_) col4row[t] = -1;
    __syncthreads();

    // ---- greedy phase: row i wants column arg_i; lowest row index wins ----
    unsigned long long myarg = 0;
    if (t < G_ && t < nact) {
        myarg = __ldg(g_rowarg + b * G_ + t);
        u[t] = ord2f((unsigned int)(myarg >> 32));     // u[i] = row min (exact)
        atomicMin(&colowner[(int)(myarg & 0xffffffffu)], t);
    }
    __syncthreads();
    if (t < G_ && t < nact) {
        int j = (int)(myarg & 0xffffffffu);
        if (colowner[j] == t) { col4row[t] = j; row4col[j] = t; }
    }
    __syncthreads();

    // ---- augment the (rare) unassigned rows ----
    for (int i = 0; i < nact; ++i) {
        if (col4row[i] >= 0) continue;

        #pragma unroll
        for (int k = 0; k < CPT; k++) { shreg[k] = BIGF; pathreg[k] = -1; }
        scmask = 0u;
        if (t < G_) SR[t] = 0;
        __syncthreads();           // barrier A

        int   cur    = i;
        float ucur   = u[i];
        float minval = 0.0f;
        int   sink   = -1;
        int   parity = 0;

        while (sink < 0) {
            if (t == 0) SR[cur] = 1;
            const float* crow = cost + (size_t)cur * P_;

            float c[CPT];
            #pragma unroll
            for (int k = 0; k < CPT; k++) c[k] = __ldg(crow + t + k * NT);

            float bestv = INFF;
            int   bestj = P_;
            #pragma unroll
            for (int k = 0; k < CPT; k++) {
                if (!((scmask >> k) & 1u)) {
                    float red = ((minval + c[k]) - ucur) - vreg[k];
                    if (red < shreg[k]) { shreg[k] = red; pathreg[k] = cur; }
                    if (shreg[k] < bestv) { bestv = shreg[k]; bestj = t + k * NT; }
                }
            }
            unsigned int key    = f2ord(bestv);
            unsigned int minkey = __reduce_min_sync(0xffffffffu, key);
            unsigned int jc     = (key == minkey) ? (unsigned int)bestj : 0xffffffffu;
            unsigned int minj   = __reduce_min_sync(0xffffffffu, jc);

            if ((t & 31) == 0) {
                int r = row4col[minj];
                float ur = (r >= 0) ? u[r] : 0.0f;
                partials[parity * NW + (t >> 5)] =
                    make_uint4(minkey, minj, (unsigned int)r, __float_as_uint(ur));
            }
            __syncthreads();

            uint4 best = partials[parity * NW];
            #pragma unroll
            for (int w = 1; w < NW; w++) {
                uint4 pw = partials[parity * NW + w];
                if (pw.x < best.x || (pw.x == best.x && pw.y < best.y)) best = pw;
            }
            minval = ord2f(best.x);
            int bj = (int)best.y;
            if ((bj & (NT - 1)) == t) scmask |= 1u << (bj >> 8);
            if ((int)best.z < 0) { sink = bj; }
            else { cur = (int)best.z; ucur = __uint_as_float(best.w); }
            parity ^= 1;
        }

        #pragma unroll
        for (int k = 0; k < CPT; k++) {
            sh_dump[t + k * NT]   = shreg[k];
            path_dump[t + k * NT] = pathreg[k];
        }
        __syncthreads();           // barrier B

        // dual updates (standard JV, valid for arbitrary feasible starting duals)
        if (t == 0) u[i] += minval;
        if (t < G_ && t != i && SR[t]) {
            int c4 = col4row[t]; if (c4 < 0) c4 = 0;
            u[t] = (u[t] + minval) - sh_dump[c4];
        }
        #pragma unroll
        for (int k = 0; k < CPT; k++)
            if ((scmask >> k) & 1u) vreg[k] = vreg[k] - (minval - shreg[k]);
        __syncthreads();           // barrier C

        if (t == 0) {
            int j = sink;
            while (true) {
                int r = path_dump[j];
                row4col[j] = r;
                int jn = col4row[r];
                col4row[r] = j;
                if (r == i) break;
                j = jn;
            }
        }
        __syncthreads();           // make augment visible before next row's test
    }

    // outputs: region 0 = per_prop_gt_inds (as float), region 1 = matched mask
    float* oi = out + (size_t)b * P_;
    float* om = out + (size_t)B_ * P_ + (size_t)b * P_;
    for (int j = t; j < P_; j += NT) { oi[j] = 0.0f; om[j] = 0.0f; }
    __syncthreads();
    if (t < G_ && t < nact) {
        int p = col4row[t];
        if (p >= 0) { oi[p] = (float)t; om[p] = 1.0f; }
    }
}

// ---------------------------------------------------------------------------
static const int MATCHER_SMEM =
    P_ * 4 * 3                 /* row4col, sh_dump, path_dump/colowner */
    + G_ * 4 * 2               /* u, col4row */
    + 2 * NW * 16              /* uint4 partials */
    + G_ + 64;                 /* SR + pad */

extern "C" void kernel_launch(void* const* d_in, const int* in_sizes, int n_in,
                              void* d_out, int out_size) {
    const float* cd   = (const float*)d_in[0];
    const float* gi   = (const float*)d_in[1];
    const int*   nact = (const int*)d_in[2];

    float* out = (float*)d_out;                  // [2, B, P] float32

    dim3 tb(32, 32);
    dim3 gb(P_ / 32, G_ / 32, B_);
    cost_transpose_kernel<<<gb, tb>>>(cd, gi);

    row_argmin_kernel<<<dim3(G_, B_), NT>>>();

    cudaFuncSetAttribute(matcher_kernel,
                         cudaFuncAttributeMaxDynamicSharedMemorySize, MATCHER_SMEM);
    matcher_kernel<<<B_, NT, MATCHER_SMEM>>>(nact, out);
}

// round 6
// speedup vs baseline: 10.4735x; 1.1199x over previous
#include <cuda_runtime.h>
#include <cuda_bf16.h>

#define B_ 8
#define P_ 4096
#define G_ 96
#define NT 256
#define NW (NT / 32)
#define CPT (P_ / NT)
#define BIGF 1e9f
#define INFF 3.402823466e+38f

__device__ float g_costT[(size_t)B_ * G_ * P_];
__device__ unsigned long long g_rowarg[B_ * G_];   // packed (f2ord(min)<<32) | argmin

__device__ __forceinline__ unsigned int f2ord(float f) {
    unsigned int u = __float_as_uint(f);
    return ((int)u < 0) ? ~u : (u ^ 0x80000000u);
}
__device__ __forceinline__ float ord2f(unsigned int k) {
    unsigned int u = (k & 0x80000000u) ? (k ^ 0x80000000u) : ~k;
    return __uint_as_float(u);
}

// ---------------------------------------------------------------------------
// Kernel 1: fused cost + transpose, 4 elements per thread (ILP + MLP).
// costT[b][g][p] = cd[b][p][g] - 2*gi[b][p][g]
// ---------------------------------------------------------------------------
__global__ __launch_bounds__(256, 8)
void cost_transpose_kernel(const float* __restrict__ cd,
                           const float* __restrict__ gi) {
    __shared__ float tile[32][33];
    const int b  = blockIdx.z;
    const int p0 = blockIdx.x * 32;
    const int g0 = blockIdx.y * 32;          // G_=96: 3 tiles along g
    const int tx = threadIdx.x;              // 0..31
    const int ty = threadIdx.y;              // 0..7

    // load 4 p-rows per thread, coalesced along g
    float c[4], g[4];
    #pragma unroll
    for (int r = 0; r < 4; r++) {
        size_t iidx = ((size_t)b * P_ + (p0 + ty + 8 * r)) * G_ + (g0 + tx);
        c[r] = __ldg(cd + iidx);
        g[r] = __ldg(gi + iidx);
    }
    #pragma unroll
    for (int r = 0; r < 4; r++)
        tile[ty + 8 * r][tx] = c[r] - 2.0f * g[r];   // 2*g exact in fp32
    __syncthreads();

    // write 4 g-rows per thread, coalesced along p
    #pragma unroll
    for (int r = 0; r < 4; r++)
        g_costT[((size_t)b * G_ + (g0 + ty + 8 * r)) * P_ + (p0 + tx)]
            = tile[tx][ty + 8 * r];
}

// ---------------------------------------------------------------------------
// Kernel 2: per-row argmin over P columns (L2-resident). grid=(G_, B_).
// ---------------------------------------------------------------------------
__global__ __launch_bounds__(NT, 8)
void row_argmin_kernel() {
    __shared__ unsigned long long part[NW];
    const int g = blockIdx.x, b = blockIdx.y;
    const int t = threadIdx.x;
    const float* crow = g_costT + ((size_t)b * G_ + g) * P_;

    float bestv = INFF;
    int   bestj = 0;
    #pragma unroll
    for (int k = 0; k < CPT; k++) {
        float c = __ldg(crow + t + k * NT);
        if (c < bestv) { bestv = c; bestj = t + k * NT; }  // ascending j keeps first
    }
    unsigned long long pk = ((unsigned long long)f2ord(bestv) << 32) | (unsigned int)bestj;
    #pragma unroll
    for (int off = 16; off; off >>= 1) {
        unsigned long long o = __shfl_down_sync(0xffffffffu, pk, off);
        if (o < pk) pk = o;
    }
    if ((t & 31) == 0) part[t >> 5] = pk;
    __syncthreads();
    if (t == 0) {
        #pragma unroll
        for (int w = 1; w < NW; w++) if (part[w] < pk) pk = part[w];
        g_rowarg[b * G_ + g] = pk;
    }
}

// ---------------------------------------------------------------------------
// Kernel 3: one block per batch. Greedy dual-feasible init (u[i]=rowmin, v=0),
// then JV shortest augmenting path only for conflicted rows.
// ---------------------------------------------------------------------------
__global__ __launch_bounds__(NT, 1)
void matcher_kernel(const int* __restrict__ nactual,
                    float* __restrict__ out) {
    extern __shared__ char smem[];
    int*   row4col  = (int*)smem;                      // [P_]
    float* sh_dump  = (float*)(row4col + P_);          // [P_]
    int*   path_dump= (int*)(sh_dump + P_);            // [P_] (aliased as colowner in greedy)
    float* u        = (float*)(path_dump + P_);        // [G_]
    int*   col4row  = (int*)(u + G_);                  // [G_]
    uint4* partials = (uint4*)(col4row + G_);          // [2][NW]
    unsigned char* SR = (unsigned char*)(partials + 2 * NW); // [G_]

    const int b = blockIdx.x;
    const int t = threadIdx.x;
    const float* cost = g_costT + (size_t)b * G_ * P_;
    const int nact = nactual[b];

    float vreg[CPT];
    float shreg[CPT];
    int   pathreg[CPT];
    unsigned int scmask;

    #pragma unroll
    for (int k = 0; k < CPT; k++) vreg[k] = 0.0f;
    int* colowner = path_dump;
    for (int j = t; j < P_; j += NT) { row4col[j] = -1; colowner[j] = 0x7fffffff; }
    if (t < G_) col4row[t] = -1;
    __syncthreads();

    // ---- greedy phase: row i wants column arg_i; lowest row index wins ----
    unsigned long long myarg = 0;
    if (t < G_ && t < nact) {
        myarg = __ldg(g_rowarg + b * G_ + t);
        u[t] = ord2f((unsigned int)(myarg >> 32));     // u[i] = row min (exact)
        atomicMin(&colowner[(int)(myarg & 0xffffffffu)], t);
    }
    __syncthreads();
    if (t < G_ && t < nact) {
        int j = (int)(myarg & 0xffffffffu);
        if (colowner[j] == t) { col4row[t] = j; row4col[j] = t; }
    }
    __syncthreads();

    // ---- augment the (rare) unassigned rows ----
    for (int i = 0; i < nact; ++i) {
        if (col4row[i] >= 0) continue;

        #pragma unroll
        for (int k = 0; k < CPT; k++) { shreg[k] = BIGF; pathreg[k] = -1; }
        scmask = 0u;
        if (t < G_) SR[t] = 0;
        __syncthreads();           // barrier A

        int   cur    = i;
        float ucur   = u[i];
        float minval = 0.0f;
        int   sink   = -1;
        int   parity = 0;

        while (sink < 0) {
            if (t == 0) SR[cur] = 1;
            const float* crow = cost + (size_t)cur * P_;

            float c[CPT];
            #pragma unroll
            for (int k = 0; k < CPT; k++) c[k] = __ldg(crow + t + k * NT);

            float bestv = INFF;
            int   bestj = P_;
            #pragma unroll
            for (int k = 0; k < CPT; k++) {
                if (!((scmask >> k) & 1u)) {
                    float red = ((minval + c[k]) - ucur) - vreg[k];
                    if (red < shreg[k]) { shreg[k] = red; pathreg[k] = cur; }
                    if (shreg[k] < bestv) { bestv = shreg[k]; bestj = t + k * NT; }
                }
            }
            unsigned int key    = f2ord(bestv);
            unsigned int minkey = __reduce_min_sync(0xffffffffu, key);
            unsigned int jc     = (key == minkey) ? (unsigned int)bestj : 0xffffffffu;
            unsigned int minj   = __reduce_min_sync(0xffffffffu, jc);

            if ((t & 31) == 0) {
                int r = row4col[minj];
                float ur = (r >= 0) ? u[r] : 0.0f;
                partials[parity * NW + (t >> 5)] =
                    make_uint4(minkey, minj, (unsigned int)r, __float_as_uint(ur));
            }
            __syncthreads();

            uint4 best = partials[parity * NW];
            #pragma unroll
            for (int w = 1; w < NW; w++) {
                uint4 pw = partials[parity * NW + w];
                if (pw.x < best.x || (pw.x == best.x && pw.y < best.y)) best = pw;
            }
            minval = ord2f(best.x);
            int bj = (int)best.y;
            if ((bj & (NT - 1)) == t) scmask |= 1u << (bj >> 8);
            if ((int)best.z < 0) { sink = bj; }
            else { cur = (int)best.z; ucur = __uint_as_float(best.w); }
            parity ^= 1;
        }

        #pragma unroll
        for (int k = 0; k < CPT; k++) {
            sh_dump[t + k * NT]   = shreg[k];
            path_dump[t + k * NT] = pathreg[k];
        }
        __syncthreads();           // barrier B

        // dual updates (standard JV, valid for arbitrary feasible starting duals)
        if (t == 0) u[i] += minval;
        if (t < G_ && t != i && SR[t]) {
            int c4 = col4row[t]; if (c4 < 0) c4 = 0;
            u[t] = (u[t] + minval) - sh_dump[c4];
        }
        #pragma unroll
        for (int k = 0; k < CPT; k++)
            if ((scmask >> k) & 1u) vreg[k] = vreg[k] - (minval - shreg[k]);
        __syncthreads();           // barrier C

        if (t == 0) {
            int j = sink;
            while (true) {
                int r = path_dump[j];
                row4col[j] = r;
                int jn = col4row[r];
                col4row[r] = j;
                if (r == i) break;
                j = jn;
            }
        }
        __syncthreads();           // make augment visible before next row's test
    }

    // outputs: region 0 = per_prop_gt_inds (as float), region 1 = matched mask
    float* oi = out + (size_t)b * P_;
    float* om = out + (size_t)B_ * P_ + (size_t)b * P_;
    for (int j = t; j < P_; j += NT) { oi[j] = 0.0f; om[j] = 0.0f; }
    __syncthreads();
    if (t < G_ && t < nact) {
        int p = col4row[t];
        if (p >= 0) { oi[p] = (float)t; om[p] = 1.0f; }
    }
}

// ---------------------------------------------------------------------------
static const int MATCHER_SMEM =
    P_ * 4 * 3                 /* row4col, sh_dump, path_dump/colowner */
    + G_ * 4 * 2               /* u, col4row */
    + 2 * NW * 16              /* uint4 partials */
    + G_ + 64;                 /* SR + pad */

extern "C" void kernel_launch(void* const* d_in, const int* in_sizes, int n_in,
                              void* d_out, int out_size) {
    const float* cd   = (const float*)d_in[0];
    const float* gi   = (const float*)d_in[1];
    const int*   nact = (const int*)d_in[2];

    float* out = (float*)d_out;                  // [2, B, P] float32

    dim3 tb(32, 8);
    dim3 gb(P_ / 32, G_ / 32, B_);
    cost_transpose_kernel<<<gb, tb>>>(cd, gi);

    row_argmin_kernel<<<dim3(G_, B_), NT>>>();

    cudaFuncSetAttribute(matcher_kernel,
                         cudaFuncAttributeMaxDynamicSharedMemorySize, MATCHER_SMEM);
    matcher_kernel<<<B_, NT, MATCHER_SMEM>>>(nact, out);
}